// round 11
// baseline (speedup 1.0000x reference)
#include <cuda_runtime.h>

// Fixed shapes: n=2, C=4, d=96, h=160, w=160
#define DHW      2457600           // 96*160*160
#define DHW4     614400            // DHW / 4
#define NB       2
#define NC       4
#define TOTAL_VOX 4915200.0        // NB * DHW
#define SMOOTH   1e-5

#define BLOCKS_X 600               // 600*256*4 == DHW4 exactly
#define NBLOCKS  (BLOCKS_X * NB)   // 1200
#define TPB      256
#define THREADS_PER_BATCH (BLOCKS_X * TPB)   // 153600

// Per-block partial sums — every slot written unconditionally every run,
// so no zero-initialization kernel is needed.
// layout: [block][16] where 16 accumulators are:
// [0..3] intersect[c]  [4..7] prob_sum[c]  [8..11] count[c]
// [12] pos_cnt [13] neg_cnt [14] bce_pos_sum [15] bce_neg_sum
__device__ float g_part[NBLOCKS][16];
// Completion counter: statically 0; last block resets it to 0 -> graph-replay safe.
__device__ unsigned int g_count;

__global__ void __launch_bounds__(TPB)
fused_kernel(const float* __restrict__ segin,
             const float* __restrict__ edgein,
             const int*   __restrict__ segmask,
             const int*   __restrict__ edgemask,
             float* __restrict__ out) {
    float inter0 = 0.f, inter1 = 0.f, inter2 = 0.f, inter3 = 0.f;
    float psum0  = 0.f, psum1  = 0.f, psum2  = 0.f, psum3  = 0.f;
    float cnt0   = 0.f, cnt1   = 0.f, cnt2   = 0.f, cnt3   = 0.f;
    float posc = 0.f, negc = 0.f, bcep = 0.f, bcen = 0.f;

    const int b = blockIdx.y;
    const float4* s  = (const float4*)(segin   + (size_t)b * NC * DHW);
    const float4* e  = (const float4*)(edgein  + (size_t)b * DHW);
    const int4*   tm = (const int4*)  (segmask + (size_t)b * DHW);
    const int4*   em = (const int4*)  (edgemask+ (size_t)b * DHW);

    const int base = blockIdx.x * TPB + threadIdx.x;

    #pragma unroll
    for (int k = 0; k < 4; k++) {
        const int v = base + k * THREADS_PER_BATCH;

        float4 x0 = __ldg(&s[v]);
        float4 x1 = __ldg(&s[v +     DHW4]);
        float4 x2 = __ldg(&s[v + 2 * DHW4]);
        float4 x3 = __ldg(&s[v + 3 * DHW4]);
        int4   t  = __ldg(&tm[v]);
        float4 ev = __ldg(&e[v]);
        int4   et = __ldg(&em[v]);

        const float a0[4] = {x0.x, x0.y, x0.z, x0.w};
        const float a1[4] = {x1.x, x1.y, x1.z, x1.w};
        const float a2[4] = {x2.x, x2.y, x2.z, x2.w};
        const float a3[4] = {x3.x, x3.y, x3.z, x3.w};
        const int   tt[4] = {t.x, t.y, t.z, t.w};
        const float ee[4] = {ev.x, ev.y, ev.z, ev.w};
        const int   eb[4] = {et.x, et.y, et.z, et.w};

        #pragma unroll
        for (int j = 0; j < 4; j++) {
            // --- softmax over 4 channels (inputs ~N(0,1): no max-shift needed) ---
            float p0 = __expf(a0[j]);
            float p1 = __expf(a1[j]);
            float p2 = __expf(a2[j]);
            float p3 = __expf(a3[j]);
            float inv = __frcp_rn(p0 + p1 + p2 + p3);
            p0 *= inv; p1 *= inv; p2 *= inv; p3 *= inv;

            psum0 += p0; psum1 += p1; psum2 += p2; psum3 += p3;

            const int c = tt[j];
            if (c == 0) { inter0 += p0; cnt0 += 1.f; }
            if (c == 1) { inter1 += p1; cnt1 += 1.f; }
            if (c == 2) { inter2 += p2; cnt2 += 1.f; }
            if (c == 3) { inter3 += p3; cnt3 += 1.f; }

            // --- numerically stable BCE-with-logits ---
            const float x = ee[j];
            const int   y = eb[j];
            float bce = fmaxf(x, 0.f) - x * (float)(y == 1)
                      + log1pf(__expf(-fabsf(x)));
            if (y == 1)      { posc += 1.f; bcep += bce; }
            else if (y == 0) { negc += 1.f; bcen += bce; }
        }
    }

    // ---- block reduction of 16 accumulators ----
    float acc[16] = {inter0, inter1, inter2, inter3,
                     psum0,  psum1,  psum2,  psum3,
                     cnt0,   cnt1,   cnt2,   cnt3,
                     posc,   negc,   bcep,   bcen};

    #pragma unroll
    for (int k = 0; k < 16; k++) {
        #pragma unroll
        for (int o = 16; o > 0; o >>= 1)
            acc[k] += __shfl_down_sync(0xFFFFFFFFu, acc[k], o);
    }

    __shared__ float sh[8][16];
    const int warp = threadIdx.x >> 5;
    const int lane = threadIdx.x & 31;
    if (lane == 0) {
        #pragma unroll
        for (int k = 0; k < 16; k++) sh[warp][k] = acc[k];
    }
    __syncthreads();

    const int blk = blockIdx.y * BLOCKS_X + blockIdx.x;
    if (threadIdx.x < 16) {
        float v = 0.f;
        #pragma unroll
        for (int w = 0; w < 8; w++) v += sh[w][threadIdx.x];
        g_part[blk][threadIdx.x] = v;
    }

    // ---- last-block-finalizes pattern ----
    __shared__ bool is_last;
    __threadfence();                       // make partials visible
    if (threadIdx.x == 0) {
        unsigned int old = atomicAdd(&g_count, 1u);
        is_last = (old == (unsigned)(NBLOCKS - 1));
    }
    __syncthreads();
    if (!is_last) return;

    __threadfence();                       // acquire: see all partials

    // 256 threads: thread = (slot 0..15, acc 0..15); each sums 75 blocks.
    const int a    = threadIdx.x & 15;
    const int slot = threadIdx.x >> 4;
    double ds = 0.0;
    for (int jb = slot; jb < NBLOCKS; jb += 16)
        ds += (double)g_part[jb][a];

    __shared__ double dsh[16][16];         // [slot][acc]
    dsh[slot][a] = ds;
    __syncthreads();

    if (threadIdx.x == 0) {
        double tot[16];
        #pragma unroll
        for (int kk = 0; kk < 16; kk++) {
            double t2 = 0.0;
            #pragma unroll
            for (int s2 = 0; s2 < 16; s2++) t2 += dsh[s2][kk];
            tot[kk] = t2;
        }
        // soft dice
        double dice_sum = 0.0;
        #pragma unroll
        for (int c = 0; c < NC; c++) {
            double inter = tot[c];
            double denom = tot[4 + c] + tot[8 + c];
            dice_sum += (2.0 * inter + SMOOTH) / (denom + SMOOTH);
        }
        out[0] = (float)(1.0 - dice_sum / (double)NC);
        // weighted BCE: mean(weight*bce) = (neg*S_pos + pos*S_neg)/(sum*total)
        double pos = tot[12], neg = tot[13];
        double sum = pos + neg;
        out[1] = (float)((neg * tot[14] + pos * tot[15]) / (sum * TOTAL_VOX));

        g_count = 0;                       // reset for next graph replay
    }
}

extern "C" void kernel_launch(void* const* d_in, const int* in_sizes, int n_in,
                              void* d_out, int out_size) {
    const float* segin    = (const float*)d_in[0];
    const float* edgein   = (const float*)d_in[1];
    const int*   segmask  = (const int*)d_in[2];
    const int*   edgemask = (const int*)d_in[3];
    float* out = (float*)d_out;

    dim3 grid(BLOCKS_X, NB);
    fused_kernel<<<grid, TPB>>>(segin, edgein, segmask, edgemask, out);
}

// round 16
// speedup vs baseline: 1.0102x; 1.0102x over previous
#include <cuda_runtime.h>

// Fixed shapes: n=2, C=4, d=96, h=160, w=160
#define DHW      2457600           // 96*160*160
#define DHW4     614400            // DHW / 4
#define NB       2
#define NC       4
#define TOTAL_VOX 4915200.0        // NB * DHW
#define SMOOTH   1e-5

#define BLOCKS_X 592
#define NBLOCKS  (BLOCKS_X * NB)   // 1184
#define TPB      256

// Per-block partial sums — written unconditionally every run, read only by
// the finalize kernel launched afterwards (kernel boundary = full ordering).
// layout: [block][16]:
// [0..3] intersect[c]  [4..7] prob_sum[c]  [8..11] count[c]
// [12] pos_cnt [13] neg_cnt [14] bce_pos_sum [15] bce_neg_sum
__device__ float g_part[NBLOCKS][16];

__global__ void __launch_bounds__(TPB)
reduce_kernel(const float* __restrict__ segin,
              const float* __restrict__ edgein,
              const int*   __restrict__ segmask,
              const int*   __restrict__ edgemask) {
    float inter0 = 0.f, inter1 = 0.f, inter2 = 0.f, inter3 = 0.f;
    float psum0  = 0.f, psum1  = 0.f, psum2  = 0.f, psum3  = 0.f;
    float cnt0   = 0.f, cnt1   = 0.f, cnt2   = 0.f, cnt3   = 0.f;
    float posc = 0.f, negc = 0.f, bcep = 0.f, bcen = 0.f;

    // batch handled by gridDim.y -> no integer division in the loop
    const int b = blockIdx.y;
    const float4* s  = (const float4*)(segin   + (size_t)b * NC * DHW);
    const float4* e  = (const float4*)(edgein  + (size_t)b * DHW);
    const int4*   tm = (const int4*)  (segmask + (size_t)b * DHW);
    const int4*   em = (const int4*)  (edgemask+ (size_t)b * DHW);

    const int stride = gridDim.x * blockDim.x;

    // Rolled grid-stride loop — proven fast in R3; do NOT fully unroll
    // (R11 showed full unroll chokes on register-limited load batching).
    for (int v = blockIdx.x * blockDim.x + threadIdx.x; v < DHW4; v += stride) {
        float4 x0 = __ldg(&s[v]);
        float4 x1 = __ldg(&s[v +     DHW4]);
        float4 x2 = __ldg(&s[v + 2 * DHW4]);
        float4 x3 = __ldg(&s[v + 3 * DHW4]);
        int4   t  = __ldg(&tm[v]);
        float4 ev = __ldg(&e[v]);
        int4   et = __ldg(&em[v]);

        const float a0[4] = {x0.x, x0.y, x0.z, x0.w};
        const float a1[4] = {x1.x, x1.y, x1.z, x1.w};
        const float a2[4] = {x2.x, x2.y, x2.z, x2.w};
        const float a3[4] = {x3.x, x3.y, x3.z, x3.w};
        const int   tt[4] = {t.x, t.y, t.z, t.w};
        const float ee[4] = {ev.x, ev.y, ev.z, ev.w};
        const int   eb[4] = {et.x, et.y, et.z, et.w};

        #pragma unroll
        for (int j = 0; j < 4; j++) {
            // --- softmax over 4 channels ---
            float ca = a0[j], cb = a1[j], cc = a2[j], cd = a3[j];
            float m  = fmaxf(fmaxf(ca, cb), fmaxf(cc, cd));
            float p0 = __expf(ca - m);
            float p1 = __expf(cb - m);
            float p2 = __expf(cc - m);
            float p3 = __expf(cd - m);
            float inv = __frcp_rn(p0 + p1 + p2 + p3);
            p0 *= inv; p1 *= inv; p2 *= inv; p3 *= inv;

            psum0 += p0; psum1 += p1; psum2 += p2; psum3 += p3;

            const int c = tt[j];
            if (c == 0) { inter0 += p0; cnt0 += 1.f; }
            if (c == 1) { inter1 += p1; cnt1 += 1.f; }
            if (c == 2) { inter2 += p2; cnt2 += 1.f; }
            if (c == 3) { inter3 += p3; cnt3 += 1.f; }

            // --- numerically stable BCE-with-logits ---
            const float x = ee[j];
            const int   y = eb[j];
            float bce = fmaxf(x, 0.f) - x * (float)(y == 1)
                      + log1pf(__expf(-fabsf(x)));
            if (y == 1)      { posc += 1.f; bcep += bce; }
            else if (y == 0) { negc += 1.f; bcen += bce; }
        }
    }

    // ---- block reduction of 16 accumulators ----
    float acc[16] = {inter0, inter1, inter2, inter3,
                     psum0,  psum1,  psum2,  psum3,
                     cnt0,   cnt1,   cnt2,   cnt3,
                     posc,   negc,   bcep,   bcen};

    #pragma unroll
    for (int k = 0; k < 16; k++) {
        #pragma unroll
        for (int o = 16; o > 0; o >>= 1)
            acc[k] += __shfl_down_sync(0xFFFFFFFFu, acc[k], o);
    }

    __shared__ float sh[8][16];
    const int warp = threadIdx.x >> 5;
    const int lane = threadIdx.x & 31;
    if (lane == 0) {
        #pragma unroll
        for (int k = 0; k < 16; k++) sh[warp][k] = acc[k];
    }
    __syncthreads();

    const int blk = blockIdx.y * BLOCKS_X + blockIdx.x;
    if (threadIdx.x < 16) {
        float v = 0.f;
        #pragma unroll
        for (int w = 0; w < 8; w++) v += sh[w][threadIdx.x];
        g_part[blk][threadIdx.x] = v;   // plain store; next kernel reads it
    }
}

__global__ void __launch_bounds__(TPB)
finalize_kernel(float* __restrict__ out) {
    // 256 threads: thread = (slot 0..15, acc 0..15); each sums 74 blocks.
    const int a    = threadIdx.x & 15;
    const int slot = threadIdx.x >> 4;
    double ds = 0.0;
    for (int jb = slot; jb < NBLOCKS; jb += 16)
        ds += (double)g_part[jb][a];

    __shared__ double dsh[16][16];         // [slot][acc]
    dsh[slot][a] = ds;
    __syncthreads();

    if (threadIdx.x == 0) {
        double tot[16];
        #pragma unroll
        for (int kk = 0; kk < 16; kk++) {
            double t2 = 0.0;
            #pragma unroll
            for (int s2 = 0; s2 < 16; s2++) t2 += dsh[s2][kk];
            tot[kk] = t2;
        }
        // soft dice
        double dice_sum = 0.0;
        #pragma unroll
        for (int c = 0; c < NC; c++) {
            double inter = tot[c];
            double denom = tot[4 + c] + tot[8 + c];
            dice_sum += (2.0 * inter + SMOOTH) / (denom + SMOOTH);
        }
        out[0] = (float)(1.0 - dice_sum / (double)NC);
        // weighted BCE: mean(weight*bce) = (neg*S_pos + pos*S_neg)/(sum*total)
        double pos = tot[12], neg = tot[13];
        double sum = pos + neg;
        out[1] = (float)((neg * tot[14] + pos * tot[15]) / (sum * TOTAL_VOX));
    }
}

extern "C" void kernel_launch(void* const* d_in, const int* in_sizes, int n_in,
                              void* d_out, int out_size) {
    const float* segin    = (const float*)d_in[0];
    const float* edgein   = (const float*)d_in[1];
    const int*   segmask  = (const int*)d_in[2];
    const int*   edgemask = (const int*)d_in[3];
    float* out = (float*)d_out;

    dim3 grid(BLOCKS_X, NB);
    reduce_kernel<<<grid, TPB>>>(segin, edgein, segmask, edgemask);
    finalize_kernel<<<1, TPB>>>(out);
}